// round 15
// baseline (speedup 1.0000x reference)
#include <cuda_runtime.h>
#include <cuda_fp16.h>
#include <math.h>
#include <stdint.h>

#define BSZ 16
#define SEQ 256
#define HID 768
#define TOK (BSZ*SEQ)      // 4096
#define FFN 3072
#define NH 12
#define HD 64
#define NT 9
#define NLAYERS 6

#define WQKV_CNT (NLAYERS*HID*3*HID)
#define WO_CNT   (NLAYERS*HID*HID)
#define WFF1_CNT (NLAYERS*HID*FFN)
#define WFF2_CNT (NLAYERS*FFN*HID)
#define WTOT_CNT (WQKV_CNT+WO_CNT+WFF1_CNT+WFF2_CNT)

// ---------------- scratch ----------------
__device__ float  g_x[TOK*HID];
__device__ float  g_h1[TOK*HID];
__device__ float  g_tmp[TOK*HID];
__device__ float  g_logits[TOK*NT];
__device__ float  g_res[BSZ];
__device__ __half g_qkv16[TOK*3*HID];
__device__ __half g_x16[TOK*HID];
__device__ __half g_h116[TOK*HID];
__device__ __half g_attn16[TOK*HID];
__device__ __half g_ffn16[(size_t)TOK*FFN];
__device__ __half g_wt16[(size_t)WTOT_CNT];   // transposed fp16 weights [N][K]

// ---------------- reductions ----------------
__device__ __forceinline__ float warpReduceSum(float v){
    #pragma unroll
    for (int o = 16; o; o >>= 1) v += __shfl_xor_sync(0xffffffffu, v, o);
    return v;
}
__device__ float blockReduceSum(float v, float* sh){
    __syncthreads();
    int lane = threadIdx.x & 31, wid = threadIdx.x >> 5;
    v = warpReduceSum(v);
    if (lane == 0) sh[wid] = v;
    __syncthreads();
    int nw = blockDim.x >> 5;
    v = (threadIdx.x < nw) ? sh[threadIdx.x] : 0.0f;
    if (wid == 0) v = warpReduceSum(v);
    if (threadIdx.x == 0) sh[0] = v;
    __syncthreads();
    return sh[0];
}

__device__ __forceinline__ float gelu_tanh(float x){
    float x3 = x * x * x;
    return 0.5f * x * (1.0f + tanhf(0.7978845608028654f * (x + 0.044715f * x3)));
}

// ---------------- mma / async / ldmatrix helpers ----------------
__device__ __forceinline__ void mma_f16(float* c, const uint32_t* a, const uint32_t* b){
    asm volatile(
        "mma.sync.aligned.m16n8k16.row.col.f32.f16.f16.f32 "
        "{%0,%1,%2,%3},{%4,%5,%6,%7},{%8,%9},{%0,%1,%2,%3};"
        : "+f"(c[0]), "+f"(c[1]), "+f"(c[2]), "+f"(c[3])
        : "r"(a[0]), "r"(a[1]), "r"(a[2]), "r"(a[3]), "r"(b[0]), "r"(b[1]));
}
__device__ __forceinline__ void cpasync16(const void* smem, const void* g){
    uint32_t s = (uint32_t)__cvta_generic_to_shared(smem);
    asm volatile("cp.async.cg.shared.global [%0], [%1], 16;" :: "r"(s), "l"(g));
}
#define CP_COMMIT() asm volatile("cp.async.commit_group;")
#define CP_WAIT(n)  asm volatile("cp.async.wait_group %0;" :: "n"(n))

__device__ __forceinline__ void ldsm_x4(uint32_t* r, const __half* p){
    uint32_t a = (uint32_t)__cvta_generic_to_shared(p);
    asm volatile("ldmatrix.sync.aligned.m8n8.x4.shared.b16 {%0,%1,%2,%3}, [%4];"
        : "=r"(r[0]), "=r"(r[1]), "=r"(r[2]), "=r"(r[3]) : "r"(a));
}

// ---------------- weight transpose + fp16: W[K][N] -> Wt[N][K] ----------------
__global__ void transp_w(const float* __restrict__ src, __half* __restrict__ dst,
                         int K, int N){
    __shared__ float t[32][33];
    size_t off = (size_t)blockIdx.z * K * N;
    const float* s = src + off;
    __half* d = dst + off;
    int n0 = blockIdx.x * 32, k0 = blockIdx.y * 32;
    int tx = threadIdx.x, ty = threadIdx.y;
    #pragma unroll
    for (int i = 0; i < 4; i++){
        int k = k0 + ty + i * 8;
        t[ty + i * 8][tx] = s[(size_t)k * N + n0 + tx];
    }
    __syncthreads();
    #pragma unroll
    for (int i = 0; i < 4; i++){
        int n = n0 + ty + i * 8;
        d[(size_t)n * K + k0 + tx] = __float2half(t[tx][ty + i * 8]);
    }
}

// ---------------- embedding + LN ----------------
__global__ void embed_kernel(const int* __restrict__ ids,
                             const float* __restrict__ we,
                             const float* __restrict__ pe,
                             const float* __restrict__ gamma,
                             const float* __restrict__ beta,
                             float* __restrict__ out,
                             __half* __restrict__ out16){
    __shared__ float sh[32];
    int tok = blockIdx.x;
    int sI = tok % SEQ;
    int id = ids[tok];
    const float* wrow = we + (size_t)id * HID;
    const float* prow = pe + (size_t)sI * HID;
    float vals[3]; float lsum = 0.f;
    #pragma unroll
    for (int i = 0; i < 3; i++){
        int d = threadIdx.x + i * 256;
        float v = wrow[d] + prow[d];
        vals[i] = v; lsum += v;
    }
    float mean = blockReduceSum(lsum, sh) * (1.0f / HID);
    float lss = 0.f;
    #pragma unroll
    for (int i = 0; i < 3; i++){ float d0 = vals[i] - mean; lss += d0 * d0; }
    float var = blockReduceSum(lss, sh) * (1.0f / HID);
    float rstd = rsqrtf(var + 1e-12f);
    #pragma unroll
    for (int i = 0; i < 3; i++){
        int d = threadIdx.x + i * 256;
        float v = (vals[i] - mean) * rstd * gamma[d] + beta[d];
        out[(size_t)tok * HID + d] = v;
        out16[(size_t)tok * HID + d] = __float2half(v);
    }
}

// ---------------- residual + LN ----------------
__global__ void ln_residual_kernel(const float* __restrict__ a,
                                   const float* __restrict__ c,
                                   const float* __restrict__ gamma,
                                   const float* __restrict__ beta,
                                   float* __restrict__ out,
                                   __half* __restrict__ out16){
    __shared__ float sh[32];
    int tok = blockIdx.x;
    const float* ar = a + (size_t)tok * HID;
    const float* cr = c + (size_t)tok * HID;
    float vals[3]; float lsum = 0.f;
    #pragma unroll
    for (int i = 0; i < 3; i++){
        int d = threadIdx.x + i * 256;
        float v = ar[d] + cr[d];
        vals[i] = v; lsum += v;
    }
    float mean = blockReduceSum(lsum, sh) * (1.0f / HID);
    float lss = 0.f;
    #pragma unroll
    for (int i = 0; i < 3; i++){ float d0 = vals[i] - mean; lss += d0 * d0; }
    float var = blockReduceSum(lss, sh) * (1.0f / HID);
    float rstd = rsqrtf(var + 1e-12f);
    #pragma unroll
    for (int i = 0; i < 3; i++){
        int d = threadIdx.x + i * 256;
        float v = (vals[i] - mean) * rstd * gamma[d] + beta[d];
        out[(size_t)tok * HID + d] = v;
        out16[(size_t)tok * HID + d] = __float2half(v);
    }
}

// ========== fp16 TC GEMM, 128x128 tile, BK=64, ldmatrix fragments =============
// act: 0 = fp32 out, 1 = gelu+fp16, 2 = plain fp16
#define ASH 72
#define STG_H (128*ASH)
#define GEMM_SMEM (2 * 2 * STG_H * 2)    // 73728 B

__device__ __forceinline__ void g_fill(__half* as, __half* bs,
                                       const __half* __restrict__ A16,
                                       const __half* __restrict__ W16,
                                       int rowBase, int colBase, int K,
                                       int k0, int tid){
    int r = tid >> 1, c = (tid & 1) * 32;
    const __half* ag = A16 + (size_t)(rowBase + r) * K + k0 + c;
    __half* ad = as + r * ASH + c;
    cpasync16(ad, ag);           cpasync16(ad + 8, ag + 8);
    cpasync16(ad + 16, ag + 16); cpasync16(ad + 24, ag + 24);
    const __half* bg = W16 + (size_t)(colBase + r) * K + k0 + c;
    __half* bd = bs + r * ASH + c;
    cpasync16(bd, bg);           cpasync16(bd + 8, bg + 8);
    cpasync16(bd + 16, bg + 16); cpasync16(bd + 24, bg + 24);
}

__global__ void __launch_bounds__(256, 2)
gemm_h(const __half* __restrict__ A16,
       const __half* __restrict__ W16,
       const float* __restrict__ bias,
       float* __restrict__ C32,
       __half* __restrict__ C16,
       int M, int N, int K, int act){
    extern __shared__ char smraw[];
    __half* sm = (__half*)smraw;
    __half* As[2] = { sm,         sm + 2*STG_H };
    __half* Bs[2] = { sm + STG_H, sm + 3*STG_H };

    int tid = threadIdx.x;
    int wid = tid >> 5, lane = tid & 31;
    int warpRow = wid >> 1, warpCol = wid & 1;
    int gid = lane >> 2, tig = lane & 3;
    int rowBase = blockIdx.y * 128, colBase = blockIdx.x * 128;

    int lm_row = lane & 15;
    int lm_acol = (lane >> 4) << 3;
    int lm_brow = ((lane & 16) >> 1) + (lane & 7);
    int lm_bcol = lane & 8;

    float acc[2][8][4];
    #pragma unroll
    for (int mi = 0; mi < 2; mi++)
        #pragma unroll
        for (int ni = 0; ni < 8; ni++)
            #pragma unroll
            for (int j = 0; j < 4; j++) acc[mi][ni][j] = 0.f;

    int ntile = K >> 6;
    g_fill(As[0], Bs[0], A16, W16, rowBase, colBase, K, 0, tid);
    CP_COMMIT();

    for (int t = 0; t < ntile; t++){
        if (t + 1 < ntile){
            g_fill(As[(t+1)&1], Bs[(t+1)&1], A16, W16, rowBase, colBase, K, (t+1) << 6, tid);
            CP_COMMIT();
            CP_WAIT(1);
        } else {
            CP_WAIT(0);
        }
        __syncthreads();

        const __half* as = As[t & 1];
        const __half* bs = Bs[t & 1];
        #pragma unroll
        for (int sl = 0; sl < 4; sl++){
            int kb = sl * 16;
            uint32_t af[2][4], bf[8][2];
            #pragma unroll
            for (int mi = 0; mi < 2; mi++){
                int m0 = warpRow * 32 + mi * 16;
                ldsm_x4(af[mi], as + (m0 + lm_row) * ASH + kb + lm_acol);
            }
            #pragma unroll
            for (int np = 0; np < 4; np++){
                int n0 = warpCol * 64 + np * 16;
                uint32_t tb[4];
                ldsm_x4(tb, bs + (n0 + lm_brow) * ASH + kb + lm_bcol);
                bf[np*2][0]   = tb[0]; bf[np*2][1]   = tb[1];
                bf[np*2+1][0] = tb[2]; bf[np*2+1][1] = tb[3];
            }
            #pragma unroll
            for (int mi = 0; mi < 2; mi++)
                #pragma unroll
                for (int ni = 0; ni < 8; ni++)
                    mma_f16(acc[mi][ni], af[mi], bf[ni]);
        }
        __syncthreads();
    }

    #pragma unroll
    for (int mi = 0; mi < 2; mi++){
        int r0 = rowBase + warpRow * 32 + mi * 16 + gid;
        #pragma unroll
        for (int ni = 0; ni < 8; ni++){
            int cc = colBase + warpCol * 64 + ni * 8 + tig * 2;
            float b0 = bias[cc], b1 = bias[cc + 1];
            float v0 = acc[mi][ni][0] + b0, v1 = acc[mi][ni][1] + b1;
            float v2 = acc[mi][ni][2] + b0, v3 = acc[mi][ni][3] + b1;
            if (act == 1){
                v0 = gelu_tanh(v0); v1 = gelu_tanh(v1);
                v2 = gelu_tanh(v2); v3 = gelu_tanh(v3);
            }
            if (act == 0){
                *(float2*)&C32[(size_t)r0 * N + cc]       = make_float2(v0, v1);
                *(float2*)&C32[(size_t)(r0 + 8) * N + cc] = make_float2(v2, v3);
            } else {
                *(__half2*)&C16[(size_t)r0 * N + cc]       = __floats2half2_rn(v0, v1);
                *(__half2*)&C16[(size_t)(r0 + 8) * N + cc] = __floats2half2_rn(v2, v3);
            }
        }
    }
}

// ---------------- attention: fp16 flash attention, ldmatrix fragments ---------
#define AQ 72
#define ATT_H (128*AQ + 64*AQ + 64*AQ + 8*16*AQ)
#define ATT_SMEM (ATT_H*2 + 256*4)
__global__ void __launch_bounds__(256, 2)
attn4_kernel(const __half* __restrict__ qkv16,
             const int* __restrict__ amask,
             __half* __restrict__ out16){
    extern __shared__ char smraw[];
    __half* Qs = (__half*)smraw;
    __half* Ks = Qs + 128 * AQ;
    __half* Vt = Ks + 64 * AQ;
    __half* Pa = Vt + 64 * AQ;
    float*  bsm = (float*)(smraw + ATT_H * 2);
    int tid = threadIdx.x, w = tid >> 5, lane = tid & 31;
    int gid = lane >> 2, tig = lane & 3;
    int qb = blockIdx.x * 128, h = blockIdx.y, b = blockIdx.z;
    const size_t rs = 3 * HID;
    const __half* base = qkv16 + (size_t)b * SEQ * rs;
    __half* Pw = Pa + w * 16 * AQ;
    int m0 = w * 16;

    int lm_row = lane & 15;
    int lm_acol = (lane >> 4) << 3;
    int lm_brow = ((lane & 16) >> 1) + (lane & 7);
    int lm_bcol = lane & 8;

    bsm[tid] = (1.0f - (float)amask[b * SEQ + tid]) * -1e9f;

    {
        int r = tid >> 1, c0 = (tid & 1) * 32;
        const __half2* src = (const __half2*)(base + (size_t)(qb + r) * rs + h * HD + c0);
        __half2* dst = (__half2*)(Qs + r * AQ + c0);
        __half2 sc = __floats2half2_rn(0.125f, 0.125f);
        #pragma unroll
        for (int j = 0; j < 16; j++) dst[j] = __hmul2(src[j], sc);
    }

    float of[8][4];
    #pragma unroll
    for (int ni = 0; ni < 8; ni++)
        #pragma unroll
        for (int j = 0; j < 4; j++) of[ni][j] = 0.f;
    float mrow0 = -1e30f, mrow1 = -1e30f, lrow0 = 0.f, lrow1 = 0.f;

    for (int c = 0; c < 4; c++){
        __syncthreads();
        {
            int k = tid >> 2, d0 = (tid & 3) * 16;
            const __half* ks = base + (size_t)(c * 64 + k) * rs + HID + h * HD + d0;
            const __half* vs = base + (size_t)(c * 64 + k) * rs + 2 * HID + h * HD + d0;
            *(uint4*)(Ks + k * AQ + d0)     = *(const uint4*)ks;
            *(uint4*)(Ks + k * AQ + d0 + 8) = *(const uint4*)(ks + 8);
            __half vloc[16];
            *(uint4*)vloc       = *(const uint4*)vs;
            *(uint4*)(vloc + 8) = *(const uint4*)(vs + 8);
            #pragma unroll
            for (int j = 0; j < 16; j++)
                Vt[(d0 + j) * AQ + k] = vloc[j];
        }
        __syncthreads();

        float sc[8][4];
        #pragma unroll
        for (int ni = 0; ni < 8; ni++)
            #pragma unroll
            for (int j = 0; j < 4; j++) sc[ni][j] = 0.f;
        #pragma unroll
        for (int sl = 0; sl < 4; sl++){
            int kb = sl * 16;
            uint32_t a[4], bf[8][2];
            ldsm_x4(a, Qs + (m0 + lm_row) * AQ + kb + lm_acol);
            #pragma unroll
            for (int np = 0; np < 4; np++){
                uint32_t tb[4];
                ldsm_x4(tb, Ks + (np * 16 + lm_brow) * AQ + kb + lm_bcol);
                bf[np*2][0]   = tb[0]; bf[np*2][1]   = tb[1];
                bf[np*2+1][0] = tb[2]; bf[np*2+1][1] = tb[3];
            }
            #pragma unroll
            for (int ni = 0; ni < 8; ni++)
                mma_f16(sc[ni], a, bf[ni]);
        }

        float mx0 = -1e30f, mx1 = -1e30f;
        #pragma unroll
        for (int ni = 0; ni < 8; ni++){
            int key = c * 64 + ni * 8 + tig * 2;
            float b0 = bsm[key], b1 = bsm[key + 1];
            sc[ni][0] += b0; sc[ni][1] += b1;
            sc[ni][2] += b0; sc[ni][3] += b1;
            mx0 = fmaxf(mx0, fmaxf(sc[ni][0], sc[ni][1]));
            mx1 = fmaxf(mx1, fmaxf(sc[ni][2], sc[ni][3]));
        }
        mx0 = fmaxf(mx0, __shfl_xor_sync(0xffffffffu, mx0, 1));
        mx0 = fmaxf(mx0, __shfl_xor_sync(0xffffffffu, mx0, 2));
        mx1 = fmaxf(mx1, __shfl_xor_sync(0xffffffffu, mx1, 1));
        mx1 = fmaxf(mx1, __shfl_xor_sync(0xffffffffu, mx1, 2));
        float nm0 = fmaxf(mrow0, mx0), nm1 = fmaxf(mrow1, mx1);
        float corr0 = __expf(mrow0 - nm0), corr1 = __expf(mrow1 - nm1);
        float sum0 = 0.f, sum1 = 0.f;
        #pragma unroll
        for (int ni = 0; ni < 8; ni++){
            float p0 = __expf(sc[ni][0] - nm0);
            float p1 = __expf(sc[ni][1] - nm0);
            float p2 = __expf(sc[ni][2] - nm1);
            float p3 = __expf(sc[ni][3] - nm1);
            sum0 += p0 + p1; sum1 += p2 + p3;
            int n0 = ni * 8 + tig * 2;
            *(__half2*)(Pw + gid * AQ + n0)       = __floats2half2_rn(p0, p1);
            *(__half2*)(Pw + (gid + 8) * AQ + n0) = __floats2half2_rn(p2, p3);
        }
        sum0 += __shfl_xor_sync(0xffffffffu, sum0, 1);
        sum0 += __shfl_xor_sync(0xffffffffu, sum0, 2);
        sum1 += __shfl_xor_sync(0xffffffffu, sum1, 1);
        sum1 += __shfl_xor_sync(0xffffffffu, sum1, 2);
        lrow0 = lrow0 * corr0 + sum0;
        lrow1 = lrow1 * corr1 + sum1;
        mrow0 = nm0; mrow1 = nm1;
        #pragma unroll
        for (int ni = 0; ni < 8; ni++){
            of[ni][0] *= corr0; of[ni][1] *= corr0;
            of[ni][2] *= corr1; of[ni][3] *= corr1;
        }
        __syncwarp();

        #pragma unroll
        for (int sl = 0; sl < 4; sl++){
            int kb = sl * 16;
            uint32_t a[4], bf[8][2];
            ldsm_x4(a, Pw + lm_row * AQ + kb + lm_acol);
            #pragma unroll
            for (int np = 0; np < 4; np++){
                uint32_t tb[4];
                ldsm_x4(tb, Vt + (np * 16 + lm_brow) * AQ + kb + lm_bcol);
                bf[np*2][0]   = tb[0]; bf[np*2][1]   = tb[1];
                bf[np*2+1][0] = tb[2]; bf[np*2+1][1] = tb[3];
            }
            #pragma unroll
            for (int ni = 0; ni < 8; ni++)
                mma_f16(of[ni], a, bf[ni]);
        }
        __syncwarp();
    }

    float inv0 = 1.0f / lrow0, inv1 = 1.0f / lrow1;
    int q0 = qb + m0 + gid, q1 = q0 + 8;
    #pragma unroll
    for (int ni = 0; ni < 8; ni++){
        int d = ni * 8 + tig * 2;
        *(__half2*)&out16[(size_t)(b * SEQ + q0) * HID + h * HD + d] =
            __floats2half2_rn(of[ni][0] * inv0, of[ni][1] * inv0);
        *(__half2*)&out16[(size_t)(b * SEQ + q1) * HID + h * HD + d] =
            __floats2half2_rn(of[ni][2] * inv1, of[ni][3] * inv1);
    }
}

// ---------------- classifier ----------------
__global__ void cls_kernel(const float* __restrict__ x,
                           const float* __restrict__ W,
                           const float* __restrict__ bias,
                           float* __restrict__ logits){
    __shared__ float xs[HID];
    int tok = blockIdx.x;
    for (int d = threadIdx.x; d < HID; d += blockDim.x)
        xs[d] = x[(size_t)tok * HID + d];
    __syncthreads();
    int w = threadIdx.x >> 5, lane = threadIdx.x & 31;
    float acc = 0.f;
    for (int d = lane; d < HID; d += 32)
        acc = fmaf(xs[d], W[d * NT + w], acc);
    acc = warpReduceSum(acc);
    if (lane == 0) logits[tok * NT + w] = acc + bias[w];
}

// ---------------- CRF ----------------
__global__ void crf_kernel(const float* __restrict__ logits,
                           const int* __restrict__ labels,
                           const float* __restrict__ cstart,
                           const float* __restrict__ cend,
                           const float* __restrict__ ctrans,
                           float* __restrict__ res){
    __shared__ float score[NT];
    __shared__ float tr[NT * NT];
    __shared__ float st[NT], en[NT];
    int b = blockIdx.x, tid = threadIdx.x;
    for (int i = tid; i < NT * NT; i += 32) tr[i] = ctrans[i];
    if (tid < NT){ st[tid] = cstart[tid]; en[tid] = cend[tid]; }
    const float* lg = logits + (size_t)b * SEQ * NT;
    const int* lab = labels + b * SEQ;
    if (tid < NT) score[tid] = st[tid] + lg[tid];
    __syncwarp();
    for (int s = 1; s < SEQ; s++){
        float nxt = 0.f;
        if (tid < NT){
            float m = -INFINITY;
            #pragma unroll
            for (int i = 0; i < NT; i++) m = fmaxf(m, score[i] + tr[i * NT + tid]);
            float sum = 0.f;
            #pragma unroll
            for (int i = 0; i < NT; i++) sum += expf(score[i] + tr[i * NT + tid] - m);
            nxt = m + logf(sum) + lg[s * NT + tid];
        }
        bool msk = (lab[s] != -100);
        __syncwarp();
        if (tid < NT && msk) score[tid] = nxt;
        __syncwarp();
    }
    if (tid == 0){
        float m = -INFINITY;
        for (int t = 0; t < NT; t++) m = fmaxf(m, score[t] + en[t]);
        float sum = 0.f;
        for (int t = 0; t < NT; t++) sum += expf(score[t] + en[t] - m);
        float denom = m + logf(sum);
        int l0 = lab[0];
        int tag_prev = (l0 == -100) ? 0 : l0;
        float num = st[tag_prev] + lg[tag_prev];
        int cnt = 1;
        for (int s = 1; s < SEQ; s++){
            int ls = lab[s];
            bool msk = (ls != -100);
            int tg = msk ? ls : 0;
            if (msk){
                num += tr[tag_prev * NT + tg] + lg[s * NT + tg];
                cnt++;
            }
            tag_prev = tg;
        }
        int seq_end = cnt - 1;
        int le = lab[seq_end];
        int last_tag = (le == -100) ? 0 : le;
        num += en[last_tag];
        res[b] = num - denom;
    }
}

// ---------------- finalize ----------------
__global__ void finalize_kernel(const float* __restrict__ res,
                                const float* __restrict__ logits,
                                float* __restrict__ out, int nlog){
    int idx = blockIdx.x * blockDim.x + threadIdx.x;
    if (idx == 0){
        float s = 0.f;
        for (int b = 0; b < BSZ; b++) s += res[b];
        out[0] = -s / BSZ;
    }
    if (idx < nlog) out[1 + idx] = logits[idx];
}

// ---------------- launch ----------------
extern "C" void kernel_launch(void* const* d_in, const int* in_sizes, int n_in,
                              void* d_out, int out_size){
    const int*   input_ids = (const int*)  d_in[0];
    const int*   amask     = (const int*)  d_in[1];
    const int*   labels    = (const int*)  d_in[2];
    const float* word_emb  = (const float*)d_in[3];
    const float* pos_emb   = (const float*)d_in[4];
    const float* emb_ln_s  = (const float*)d_in[5];
    const float* emb_ln_b  = (const float*)d_in[6];
    const float* Wqkv      = (const float*)d_in[7];
    const float* bqkv      = (const float*)d_in[8];
    const float* Wo        = (const float*)d_in[9];
    const float* bo        = (const float*)d_in[10];
    const float* ln1_s     = (const float*)d_in[11];
    const float* ln1_b     = (const float*)d_in[12];
    const float* Wff1      = (const float*)d_in[13];
    const float* bff1      = (const float*)d_in[14];
    const float* Wff2      = (const float*)d_in[15];
    const float* bff2      = (const float*)d_in[16];
    const float* ln2_s     = (const float*)d_in[17];
    const float* ln2_b     = (const float*)d_in[18];
    const float* Wcls      = (const float*)d_in[19];
    const float* bcls      = (const float*)d_in[20];
    const float* crf_start = (const float*)d_in[21];
    const float* crf_end   = (const float*)d_in[22];
    const float* crf_trans = (const float*)d_in[23];

    float *x, *h1, *tmp, *logits, *res;
    __half *qkv16, *x16, *h116, *attn16, *ffn16, *wt16;
    cudaGetSymbolAddress((void**)&x,      g_x);
    cudaGetSymbolAddress((void**)&h1,     g_h1);
    cudaGetSymbolAddress((void**)&tmp,    g_tmp);
    cudaGetSymbolAddress((void**)&logits, g_logits);
    cudaGetSymbolAddress((void**)&res,    g_res);
    cudaGetSymbolAddress((void**)&qkv16,  g_qkv16);
    cudaGetSymbolAddress((void**)&x16,    g_x16);
    cudaGetSymbolAddress((void**)&h116,   g_h116);
    cudaGetSymbolAddress((void**)&attn16, g_attn16);
    cudaGetSymbolAddress((void**)&ffn16,  g_ffn16);
    cudaGetSymbolAddress((void**)&wt16,   g_wt16);

    __half* tWqkv = wt16;
    __half* tWo   = tWqkv + WQKV_CNT;
    __half* tWff1 = tWo   + WO_CNT;
    __half* tWff2 = tWff1 + WFF1_CNT;

    static int smem_set = 0;
    if (!smem_set){
        cudaFuncSetAttribute(attn4_kernel,
                             cudaFuncAttributeMaxDynamicSharedMemorySize, ATT_SMEM);
        cudaFuncSetAttribute(gemm_h,
                             cudaFuncAttributeMaxDynamicSharedMemorySize, GEMM_SMEM);
        smem_set = 1;
    }

    dim3 t328(32, 8);
    transp_w<<<dim3(3*HID/32, HID/32, NLAYERS), t328>>>(Wqkv, tWqkv, HID, 3*HID);
    transp_w<<<dim3(HID/32,   HID/32, NLAYERS), t328>>>(Wo,   tWo,   HID, HID);
    transp_w<<<dim3(FFN/32,   HID/32, NLAYERS), t328>>>(Wff1, tWff1, HID, FFN);
    transp_w<<<dim3(HID/32,   FFN/32, NLAYERS), t328>>>(Wff2, tWff2, FFN, HID);

    embed_kernel<<<TOK, 256>>>(input_ids, word_emb, pos_emb, emb_ln_s, emb_ln_b, x, x16);

    for (int l = 0; l < NLAYERS; l++){
        const __half* wqkv = tWqkv + (size_t)l * HID * 3 * HID;
        const float* bq   = bqkv + (size_t)l * 3 * HID;
        const __half* wo  = tWo   + (size_t)l * HID * HID;
        const float* bo_  = bo   + (size_t)l * HID;
        const float* s1   = ln1_s + (size_t)l * HID;
        const float* b1   = ln1_b + (size_t)l * HID;
        const __half* w1  = tWff1 + (size_t)l * HID * FFN;
        const float* bf1  = bff1 + (size_t)l * FFN;
        const __half* w2  = tWff2 + (size_t)l * FFN * HID;
        const float* bf2  = bff2 + (size_t)l * HID;
        const float* s2   = ln2_s + (size_t)l * HID;
        const float* b2   = ln2_b + (size_t)l * HID;

        // QKV: fp16 out
        gemm_h<<<dim3(3*HID/128, TOK/128), 256, GEMM_SMEM>>>(x16, wqkv, bq, nullptr, qkv16, TOK, 3*HID, HID, 2);
        // attention (fp16 in/out)
        attn4_kernel<<<dim3(SEQ/128, NH, BSZ), 256, ATT_SMEM>>>(qkv16, amask, attn16);
        // O-proj: fp32 out
        gemm_h<<<dim3(HID/128, TOK/128), 256, GEMM_SMEM>>>(attn16, wo, bo_, tmp, nullptr, TOK, HID, HID, 0);
        ln_residual_kernel<<<TOK, 256>>>(x, tmp, s1, b1, h1, h116);
        // FFN1: gelu + fp16 out
        gemm_h<<<dim3(FFN/128, TOK/128), 256, GEMM_SMEM>>>(h116, w1, bf1, nullptr, ffn16, TOK, FFN, HID, 1);
        // FFN2: fp32 out
        gemm_h<<<dim3(HID/128, TOK/128), 256, GEMM_SMEM>>>(ffn16, w2, bf2, tmp, nullptr, TOK, HID, FFN, 0);
        ln_residual_kernel<<<TOK, 256>>>(h1, tmp, s2, b2, x, x16);
    }

    cls_kernel<<<TOK, 288>>>(x, Wcls, bcls, logits);
    crf_kernel<<<BSZ, 32>>>(logits, labels, crf_start, crf_end, crf_trans, res);
    int nlog = TOK * NT;
    finalize_kernel<<<(nlog + 256) / 256, 256>>>(res, logits, (float*)d_out, nlog);
}

// round 16
// speedup vs baseline: 1.1283x; 1.1283x over previous
#include <cuda_runtime.h>
#include <cuda_fp16.h>
#include <math.h>
#include <stdint.h>

#define BSZ 16
#define SEQ 256
#define HID 768
#define TOK (BSZ*SEQ)      // 4096
#define FFN 3072
#define NH 12
#define HD 64
#define NT 9
#define NLAYERS 6

#define WQKV_CNT (NLAYERS*HID*3*HID)
#define WO_CNT   (NLAYERS*HID*HID)
#define WFF1_CNT (NLAYERS*HID*FFN)
#define WFF2_CNT (NLAYERS*FFN*HID)
#define WTOT_CNT (WQKV_CNT+WO_CNT+WFF1_CNT+WFF2_CNT)

// ---------------- scratch ----------------
__device__ float  g_x[TOK*HID];
__device__ float  g_h1[TOK*HID];
__device__ float  g_tmp[TOK*HID];
__device__ float  g_logits[TOK*NT];
__device__ float  g_res[BSZ];
__device__ __half g_qkv16[TOK*3*HID];
__device__ __half g_x16[TOK*HID];
__device__ __half g_h116[TOK*HID];
__device__ __half g_attn16[TOK*HID];
__device__ __half g_ffn16[(size_t)TOK*FFN];
__device__ __half g_wt16[(size_t)WTOT_CNT];   // transposed fp16 weights [N][K]

// ---------------- reductions ----------------
__device__ __forceinline__ float warpReduceSum(float v){
    #pragma unroll
    for (int o = 16; o; o >>= 1) v += __shfl_xor_sync(0xffffffffu, v, o);
    return v;
}
__device__ float blockReduceSum(float v, float* sh){
    __syncthreads();
    int lane = threadIdx.x & 31, wid = threadIdx.x >> 5;
    v = warpReduceSum(v);
    if (lane == 0) sh[wid] = v;
    __syncthreads();
    int nw = blockDim.x >> 5;
    v = (threadIdx.x < nw) ? sh[threadIdx.x] : 0.0f;
    if (wid == 0) v = warpReduceSum(v);
    if (threadIdx.x == 0) sh[0] = v;
    __syncthreads();
    return sh[0];
}

__device__ __forceinline__ float gelu_tanh(float x){
    float x3 = x * x * x;
    return 0.5f * x * (1.0f + tanhf(0.7978845608028654f * (x + 0.044715f * x3)));
}

// ---------------- mma / async / ldmatrix helpers ----------------
__device__ __forceinline__ void mma_f16(float* c, const uint32_t* a, const uint32_t* b){
    asm volatile(
        "mma.sync.aligned.m16n8k16.row.col.f32.f16.f16.f32 "
        "{%0,%1,%2,%3},{%4,%5,%6,%7},{%8,%9},{%0,%1,%2,%3};"
        : "+f"(c[0]), "+f"(c[1]), "+f"(c[2]), "+f"(c[3])
        : "r"(a[0]), "r"(a[1]), "r"(a[2]), "r"(a[3]), "r"(b[0]), "r"(b[1]));
}
__device__ __forceinline__ void cpasync16(const void* smem, const void* g){
    uint32_t s = (uint32_t)__cvta_generic_to_shared(smem);
    asm volatile("cp.async.cg.shared.global [%0], [%1], 16;" :: "r"(s), "l"(g));
}
#define CP_COMMIT() asm volatile("cp.async.commit_group;")
#define CP_WAIT(n)  asm volatile("cp.async.wait_group %0;" :: "n"(n))

__device__ __forceinline__ void ldsm_x4(uint32_t* r, const __half* p){
    uint32_t a = (uint32_t)__cvta_generic_to_shared(p);
    asm volatile("ldmatrix.sync.aligned.m8n8.x4.shared.b16 {%0,%1,%2,%3}, [%4];"
        : "=r"(r[0]), "=r"(r[1]), "=r"(r[2]), "=r"(r[3]) : "r"(a));
}

// ---------------- weight transpose + fp16: W[K][N] -> Wt[N][K] ----------------
__global__ void transp_w(const float* __restrict__ src, __half* __restrict__ dst,
                         int K, int N){
    __shared__ float t[32][33];
    size_t off = (size_t)blockIdx.z * K * N;
    const float* s = src + off;
    __half* d = dst + off;
    int n0 = blockIdx.x * 32, k0 = blockIdx.y * 32;
    int tx = threadIdx.x, ty = threadIdx.y;
    #pragma unroll
    for (int i = 0; i < 4; i++){
        int k = k0 + ty + i * 8;
        t[ty + i * 8][tx] = s[(size_t)k * N + n0 + tx];
    }
    __syncthreads();
    #pragma unroll
    for (int i = 0; i < 4; i++){
        int n = n0 + ty + i * 8;
        d[(size_t)n * K + k0 + tx] = __float2half(t[tx][ty + i * 8]);
    }
}

// ---------------- embedding + LN ----------------
__global__ void embed_kernel(const int* __restrict__ ids,
                             const float* __restrict__ we,
                             const float* __restrict__ pe,
                             const float* __restrict__ gamma,
                             const float* __restrict__ beta,
                             float* __restrict__ out,
                             __half* __restrict__ out16){
    __shared__ float sh[32];
    int tok = blockIdx.x;
    int sI = tok % SEQ;
    int id = ids[tok];
    const float* wrow = we + (size_t)id * HID;
    const float* prow = pe + (size_t)sI * HID;
    float vals[3]; float lsum = 0.f;
    #pragma unroll
    for (int i = 0; i < 3; i++){
        int d = threadIdx.x + i * 256;
        float v = wrow[d] + prow[d];
        vals[i] = v; lsum += v;
    }
    float mean = blockReduceSum(lsum, sh) * (1.0f / HID);
    float lss = 0.f;
    #pragma unroll
    for (int i = 0; i < 3; i++){ float d0 = vals[i] - mean; lss += d0 * d0; }
    float var = blockReduceSum(lss, sh) * (1.0f / HID);
    float rstd = rsqrtf(var + 1e-12f);
    #pragma unroll
    for (int i = 0; i < 3; i++){
        int d = threadIdx.x + i * 256;
        float v = (vals[i] - mean) * rstd * gamma[d] + beta[d];
        out[(size_t)tok * HID + d] = v;
        out16[(size_t)tok * HID + d] = __float2half(v);
    }
}

// ---------------- residual + LN ----------------
__global__ void ln_residual_kernel(const float* __restrict__ a,
                                   const float* __restrict__ c,
                                   const float* __restrict__ gamma,
                                   const float* __restrict__ beta,
                                   float* __restrict__ out,
                                   __half* __restrict__ out16){
    __shared__ float sh[32];
    int tok = blockIdx.x;
    const float* ar = a + (size_t)tok * HID;
    const float* cr = c + (size_t)tok * HID;
    float vals[3]; float lsum = 0.f;
    #pragma unroll
    for (int i = 0; i < 3; i++){
        int d = threadIdx.x + i * 256;
        float v = ar[d] + cr[d];
        vals[i] = v; lsum += v;
    }
    float mean = blockReduceSum(lsum, sh) * (1.0f / HID);
    float lss = 0.f;
    #pragma unroll
    for (int i = 0; i < 3; i++){ float d0 = vals[i] - mean; lss += d0 * d0; }
    float var = blockReduceSum(lss, sh) * (1.0f / HID);
    float rstd = rsqrtf(var + 1e-12f);
    #pragma unroll
    for (int i = 0; i < 3; i++){
        int d = threadIdx.x + i * 256;
        float v = (vals[i] - mean) * rstd * gamma[d] + beta[d];
        out[(size_t)tok * HID + d] = v;
        out16[(size_t)tok * HID + d] = __float2half(v);
    }
}

// ================= fp16 TC GEMM, 128x128 tile, BK=32, ldmatrix ================
// act: 0 = fp32 out, 1 = gelu+fp16, 2 = plain fp16
#define ASH 40
#define STG_H (128*ASH)
#define GEMM_SMEM (2 * 2 * STG_H * 2)

__device__ __forceinline__ void g_fill(__half* as, __half* bs,
                                       const __half* __restrict__ A16,
                                       const __half* __restrict__ W16,
                                       int rowBase, int colBase, int K,
                                       int k0, int tid){
    int r = tid >> 1, c = (tid & 1) * 16;
    const __half* ag = A16 + (size_t)(rowBase + r) * K + k0 + c;
    __half* ad = as + r * ASH + c;
    cpasync16(ad, ag); cpasync16(ad + 8, ag + 8);
    const __half* bg = W16 + (size_t)(colBase + r) * K + k0 + c;
    __half* bd = bs + r * ASH + c;
    cpasync16(bd, bg); cpasync16(bd + 8, bg + 8);
}

__global__ void __launch_bounds__(256, 2)
gemm_h(const __half* __restrict__ A16,
       const __half* __restrict__ W16,
       const float* __restrict__ bias,
       float* __restrict__ C32,
       __half* __restrict__ C16,
       int M, int N, int K, int act){
    extern __shared__ char smraw[];
    __half* sm = (__half*)smraw;
    __half* As[2] = { sm,         sm + 2*STG_H };
    __half* Bs[2] = { sm + STG_H, sm + 3*STG_H };

    int tid = threadIdx.x;
    int wid = tid >> 5, lane = tid & 31;
    int warpRow = wid >> 1, warpCol = wid & 1;
    int gid = lane >> 2, tig = lane & 3;
    int rowBase = blockIdx.y * 128, colBase = blockIdx.x * 128;

    int lm_row = lane & 15;
    int lm_acol = (lane >> 4) << 3;
    int lm_brow = ((lane & 16) >> 1) + (lane & 7);
    int lm_bcol = lane & 8;

    float acc[2][8][4];
    #pragma unroll
    for (int mi = 0; mi < 2; mi++)
        #pragma unroll
        for (int ni = 0; ni < 8; ni++)
            #pragma unroll
            for (int j = 0; j < 4; j++) acc[mi][ni][j] = 0.f;

    int ntile = K >> 5;
    g_fill(As[0], Bs[0], A16, W16, rowBase, colBase, K, 0, tid);
    CP_COMMIT();

    for (int t = 0; t < ntile; t++){
        if (t + 1 < ntile){
            g_fill(As[(t+1)&1], Bs[(t+1)&1], A16, W16, rowBase, colBase, K, (t+1) << 5, tid);
            CP_COMMIT();
            CP_WAIT(1);
        } else {
            CP_WAIT(0);
        }
        __syncthreads();

        const __half* as = As[t & 1];
        const __half* bs = Bs[t & 1];
        #pragma unroll
        for (int sl = 0; sl < 2; sl++){
            int kb = sl * 16;
            uint32_t af[2][4], bf[8][2];
            #pragma unroll
            for (int mi = 0; mi < 2; mi++){
                int m0 = warpRow * 32 + mi * 16;
                ldsm_x4(af[mi], as + (m0 + lm_row) * ASH + kb + lm_acol);
            }
            #pragma unroll
            for (int np = 0; np < 4; np++){
                int n0 = warpCol * 64 + np * 16;
                uint32_t tb[4];
                ldsm_x4(tb, bs + (n0 + lm_brow) * ASH + kb + lm_bcol);
                bf[np*2][0]   = tb[0]; bf[np*2][1]   = tb[1];
                bf[np*2+1][0] = tb[2]; bf[np*2+1][1] = tb[3];
            }
            #pragma unroll
            for (int mi = 0; mi < 2; mi++)
                #pragma unroll
                for (int ni = 0; ni < 8; ni++)
                    mma_f16(acc[mi][ni], af[mi], bf[ni]);
        }
        __syncthreads();
    }

    #pragma unroll
    for (int mi = 0; mi < 2; mi++){
        int r0 = rowBase + warpRow * 32 + mi * 16 + gid;
        #pragma unroll
        for (int ni = 0; ni < 8; ni++){
            int cc = colBase + warpCol * 64 + ni * 8 + tig * 2;
            float b0 = bias[cc], b1 = bias[cc + 1];
            float v0 = acc[mi][ni][0] + b0, v1 = acc[mi][ni][1] + b1;
            float v2 = acc[mi][ni][2] + b0, v3 = acc[mi][ni][3] + b1;
            if (act == 1){
                v0 = gelu_tanh(v0); v1 = gelu_tanh(v1);
                v2 = gelu_tanh(v2); v3 = gelu_tanh(v3);
            }
            if (act == 0){
                *(float2*)&C32[(size_t)r0 * N + cc]       = make_float2(v0, v1);
                *(float2*)&C32[(size_t)(r0 + 8) * N + cc] = make_float2(v2, v3);
            } else {
                *(__half2*)&C16[(size_t)r0 * N + cc]       = __floats2half2_rn(v0, v1);
                *(__half2*)&C16[(size_t)(r0 + 8) * N + cc] = __floats2half2_rn(v2, v3);
            }
        }
    }
}

// ---------------- attention: fp16 flash attention, ldmatrix fragments ---------
#define AQ 72
#define ATT_H (128*AQ + 64*AQ + 64*AQ + 8*16*AQ)
#define ATT_SMEM (ATT_H*2 + 256*4)
__global__ void __launch_bounds__(256, 2)
attn4_kernel(const __half* __restrict__ qkv16,
             const int* __restrict__ amask,
             __half* __restrict__ out16){
    extern __shared__ char smraw[];
    __half* Qs = (__half*)smraw;
    __half* Ks = Qs + 128 * AQ;
    __half* Vt = Ks + 64 * AQ;
    __half* Pa = Vt + 64 * AQ;
    float*  bsm = (float*)(smraw + ATT_H * 2);
    int tid = threadIdx.x, w = tid >> 5, lane = tid & 31;
    int gid = lane >> 2, tig = lane & 3;
    int qb = blockIdx.x * 128, h = blockIdx.y, b = blockIdx.z;
    const size_t rs = 3 * HID;
    const __half* base = qkv16 + (size_t)b * SEQ * rs;
    __half* Pw = Pa + w * 16 * AQ;
    int m0 = w * 16;

    int lm_row = lane & 15;
    int lm_acol = (lane >> 4) << 3;
    int lm_brow = ((lane & 16) >> 1) + (lane & 7);
    int lm_bcol = lane & 8;

    bsm[tid] = (1.0f - (float)amask[b * SEQ + tid]) * -1e9f;

    {
        int r = tid >> 1, c0 = (tid & 1) * 32;
        const __half2* src = (const __half2*)(base + (size_t)(qb + r) * rs + h * HD + c0);
        __half2* dst = (__half2*)(Qs + r * AQ + c0);
        __half2 sc = __floats2half2_rn(0.125f, 0.125f);
        #pragma unroll
        for (int j = 0; j < 16; j++) dst[j] = __hmul2(src[j], sc);
    }

    float of[8][4];
    #pragma unroll
    for (int ni = 0; ni < 8; ni++)
        #pragma unroll
        for (int j = 0; j < 4; j++) of[ni][j] = 0.f;
    float mrow0 = -1e30f, mrow1 = -1e30f, lrow0 = 0.f, lrow1 = 0.f;

    for (int c = 0; c < 4; c++){
        __syncthreads();
        {
            int k = tid >> 2, d0 = (tid & 3) * 16;
            const __half* ks = base + (size_t)(c * 64 + k) * rs + HID + h * HD + d0;
            const __half* vs = base + (size_t)(c * 64 + k) * rs + 2 * HID + h * HD + d0;
            *(uint4*)(Ks + k * AQ + d0)     = *(const uint4*)ks;
            *(uint4*)(Ks + k * AQ + d0 + 8) = *(const uint4*)(ks + 8);
            __half vloc[16];
            *(uint4*)vloc       = *(const uint4*)vs;
            *(uint4*)(vloc + 8) = *(const uint4*)(vs + 8);
            #pragma unroll
            for (int j = 0; j < 16; j++)
                Vt[(d0 + j) * AQ + k] = vloc[j];
        }
        __syncthreads();

        float sc[8][4];
        #pragma unroll
        for (int ni = 0; ni < 8; ni++)
            #pragma unroll
            for (int j = 0; j < 4; j++) sc[ni][j] = 0.f;
        #pragma unroll
        for (int sl = 0; sl < 4; sl++){
            int kb = sl * 16;
            uint32_t a[4], bf[8][2];
            ldsm_x4(a, Qs + (m0 + lm_row) * AQ + kb + lm_acol);
            #pragma unroll
            for (int np = 0; np < 4; np++){
                uint32_t tb[4];
                ldsm_x4(tb, Ks + (np * 16 + lm_brow) * AQ + kb + lm_bcol);
                bf[np*2][0]   = tb[0]; bf[np*2][1]   = tb[1];
                bf[np*2+1][0] = tb[2]; bf[np*2+1][1] = tb[3];
            }
            #pragma unroll
            for (int ni = 0; ni < 8; ni++)
                mma_f16(sc[ni], a, bf[ni]);
        }

        float mx0 = -1e30f, mx1 = -1e30f;
        #pragma unroll
        for (int ni = 0; ni < 8; ni++){
            int key = c * 64 + ni * 8 + tig * 2;
            float b0 = bsm[key], b1 = bsm[key + 1];
            sc[ni][0] += b0; sc[ni][1] += b1;
            sc[ni][2] += b0; sc[ni][3] += b1;
            mx0 = fmaxf(mx0, fmaxf(sc[ni][0], sc[ni][1]));
            mx1 = fmaxf(mx1, fmaxf(sc[ni][2], sc[ni][3]));
        }
        mx0 = fmaxf(mx0, __shfl_xor_sync(0xffffffffu, mx0, 1));
        mx0 = fmaxf(mx0, __shfl_xor_sync(0xffffffffu, mx0, 2));
        mx1 = fmaxf(mx1, __shfl_xor_sync(0xffffffffu, mx1, 1));
        mx1 = fmaxf(mx1, __shfl_xor_sync(0xffffffffu, mx1, 2));
        float nm0 = fmaxf(mrow0, mx0), nm1 = fmaxf(mrow1, mx1);
        float corr0 = __expf(mrow0 - nm0), corr1 = __expf(mrow1 - nm1);
        float sum0 = 0.f, sum1 = 0.f;
        #pragma unroll
        for (int ni = 0; ni < 8; ni++){
            float p0 = __expf(sc[ni][0] - nm0);
            float p1 = __expf(sc[ni][1] - nm0);
            float p2 = __expf(sc[ni][2] - nm1);
            float p3 = __expf(sc[ni][3] - nm1);
            sum0 += p0 + p1; sum1 += p2 + p3;
            int n0 = ni * 8 + tig * 2;
            *(__half2*)(Pw + gid * AQ + n0)       = __floats2half2_rn(p0, p1);
            *(__half2*)(Pw + (gid + 8) * AQ + n0) = __floats2half2_rn(p2, p3);
        }
        sum0 += __shfl_xor_sync(0xffffffffu, sum0, 1);
        sum0 += __shfl_xor_sync(0xffffffffu, sum0, 2);
        sum1 += __shfl_xor_sync(0xffffffffu, sum1, 1);
        sum1 += __shfl_xor_sync(0xffffffffu, sum1, 2);
        lrow0 = lrow0 * corr0 + sum0;
        lrow1 = lrow1 * corr1 + sum1;
        mrow0 = nm0; mrow1 = nm1;
        #pragma unroll
        for (int ni = 0; ni < 8; ni++){
            of[ni][0] *= corr0; of[ni][1] *= corr0;
            of[ni][2] *= corr1; of[ni][3] *= corr1;
        }
        __syncwarp();

        #pragma unroll
        for (int sl = 0; sl < 4; sl++){
            int kb = sl * 16;
            uint32_t a[4], bf[8][2];
            ldsm_x4(a, Pw + lm_row * AQ + kb + lm_acol);
            #pragma unroll
            for (int np = 0; np < 4; np++){
                uint32_t tb[4];
                ldsm_x4(tb, Vt + (np * 16 + lm_brow) * AQ + kb + lm_bcol);
                bf[np*2][0]   = tb[0]; bf[np*2][1]   = tb[1];
                bf[np*2+1][0] = tb[2]; bf[np*2+1][1] = tb[3];
            }
            #pragma unroll
            for (int ni = 0; ni < 8; ni++)
                mma_f16(of[ni], a, bf[ni]);
        }
        __syncwarp();
    }

    float inv0 = 1.0f / lrow0, inv1 = 1.0f / lrow1;
    int q0 = qb + m0 + gid, q1 = q0 + 8;
    #pragma unroll
    for (int ni = 0; ni < 8; ni++){
        int d = ni * 8 + tig * 2;
        *(__half2*)&out16[(size_t)(b * SEQ + q0) * HID + h * HD + d] =
            __floats2half2_rn(of[ni][0] * inv0, of[ni][1] * inv0);
        *(__half2*)&out16[(size_t)(b * SEQ + q1) * HID + h * HD + d] =
            __floats2half2_rn(of[ni][2] * inv1, of[ni][3] * inv1);
    }
}

// ---------------- classifier: writes scratch logits AND d_out+1 ---------------
__global__ void cls_kernel(const float* __restrict__ x,
                           const float* __restrict__ W,
                           const float* __restrict__ bias,
                           float* __restrict__ logits,
                           float* __restrict__ out1){
    __shared__ float xs[HID];
    int tok = blockIdx.x;
    for (int d = threadIdx.x; d < HID; d += blockDim.x)
        xs[d] = x[(size_t)tok * HID + d];
    __syncthreads();
    int w = threadIdx.x >> 5, lane = threadIdx.x & 31;
    float acc = 0.f;
    for (int d = lane; d < HID; d += 32)
        acc = fmaf(xs[d], W[d * NT + w], acc);
    acc = warpReduceSum(acc);
    if (lane == 0){
        float v = acc + bias[w];
        logits[tok * NT + w] = v;
        out1[tok * NT + w] = v;
    }
}

// ---------------- CRF ----------------
__global__ void crf_kernel(const float* __restrict__ logits,
                           const int* __restrict__ labels,
                           const float* __restrict__ cstart,
                           const float* __restrict__ cend,
                           const float* __restrict__ ctrans,
                           float* __restrict__ res){
    __shared__ float score[NT];
    __shared__ float tr[NT * NT];
    __shared__ float st[NT], en[NT];
    int b = blockIdx.x, tid = threadIdx.x;
    for (int i = tid; i < NT * NT; i += 32) tr[i] = ctrans[i];
    if (tid < NT){ st[tid] = cstart[tid]; en[tid] = cend[tid]; }
    const float* lg = logits + (size_t)b * SEQ * NT;
    const int* lab = labels + b * SEQ;
    if (tid < NT) score[tid] = st[tid] + lg[tid];
    __syncwarp();
    for (int s = 1; s < SEQ; s++){
        float nxt = 0.f;
        if (tid < NT){
            float m = -INFINITY;
            #pragma unroll
            for (int i = 0; i < NT; i++) m = fmaxf(m, score[i] + tr[i * NT + tid]);
            float sum = 0.f;
            #pragma unroll
            for (int i = 0; i < NT; i++) sum += expf(score[i] + tr[i * NT + tid] - m);
            nxt = m + logf(sum) + lg[s * NT + tid];
        }
        bool msk = (lab[s] != -100);
        __syncwarp();
        if (tid < NT && msk) score[tid] = nxt;
        __syncwarp();
    }
    if (tid == 0){
        float m = -INFINITY;
        for (int t = 0; t < NT; t++) m = fmaxf(m, score[t] + en[t]);
        float sum = 0.f;
        for (int t = 0; t < NT; t++) sum += expf(score[t] + en[t] - m);
        float denom = m + logf(sum);
        int l0 = lab[0];
        int tag_prev = (l0 == -100) ? 0 : l0;
        float num = st[tag_prev] + lg[tag_prev];
        int cnt = 1;
        for (int s = 1; s < SEQ; s++){
            int ls = lab[s];
            bool msk = (ls != -100);
            int tg = msk ? ls : 0;
            if (msk){
                num += tr[tag_prev * NT + tg] + lg[s * NT + tg];
                cnt++;
            }
            tag_prev = tg;
        }
        int seq_end = cnt - 1;
        int le = lab[seq_end];
        int last_tag = (le == -100) ? 0 : le;
        num += en[last_tag];
        res[b] = num - denom;
    }
}

// ---------------- finalize: loss only (logits already written by cls) ---------
__global__ void finalize_kernel(const float* __restrict__ res,
                                float* __restrict__ out){
    if (threadIdx.x == 0){
        float s = 0.f;
        for (int b = 0; b < BSZ; b++) s += res[b];
        out[0] = -s / BSZ;
    }
}

// ---------------- launch ----------------
extern "C" void kernel_launch(void* const* d_in, const int* in_sizes, int n_in,
                              void* d_out, int out_size){
    const int*   input_ids = (const int*)  d_in[0];
    const int*   amask     = (const int*)  d_in[1];
    const int*   labels    = (const int*)  d_in[2];
    const float* word_emb  = (const float*)d_in[3];
    const float* pos_emb   = (const float*)d_in[4];
    const float* emb_ln_s  = (const float*)d_in[5];
    const float* emb_ln_b  = (const float*)d_in[6];
    const float* Wqkv      = (const float*)d_in[7];
    const float* bqkv      = (const float*)d_in[8];
    const float* Wo        = (const float*)d_in[9];
    const float* bo        = (const float*)d_in[10];
    const float* ln1_s     = (const float*)d_in[11];
    const float* ln1_b     = (const float*)d_in[12];
    const float* Wff1      = (const float*)d_in[13];
    const float* bff1      = (const float*)d_in[14];
    const float* Wff2      = (const float*)d_in[15];
    const float* bff2      = (const float*)d_in[16];
    const float* ln2_s     = (const float*)d_in[17];
    const float* ln2_b     = (const float*)d_in[18];
    const float* Wcls      = (const float*)d_in[19];
    const float* bcls      = (const float*)d_in[20];
    const float* crf_start = (const float*)d_in[21];
    const float* crf_end   = (const float*)d_in[22];
    const float* crf_trans = (const float*)d_in[23];

    float *x, *h1, *tmp, *logits, *res;
    __half *qkv16, *x16, *h116, *attn16, *ffn16, *wt16;
    cudaGetSymbolAddress((void**)&x,      g_x);
    cudaGetSymbolAddress((void**)&h1,     g_h1);
    cudaGetSymbolAddress((void**)&tmp,    g_tmp);
    cudaGetSymbolAddress((void**)&logits, g_logits);
    cudaGetSymbolAddress((void**)&res,    g_res);
    cudaGetSymbolAddress((void**)&qkv16,  g_qkv16);
    cudaGetSymbolAddress((void**)&x16,    g_x16);
    cudaGetSymbolAddress((void**)&h116,   g_h116);
    cudaGetSymbolAddress((void**)&attn16, g_attn16);
    cudaGetSymbolAddress((void**)&ffn16,  g_ffn16);
    cudaGetSymbolAddress((void**)&wt16,   g_wt16);

    __half* tWqkv = wt16;
    __half* tWo   = tWqkv + WQKV_CNT;
    __half* tWff1 = tWo   + WO_CNT;
    __half* tWff2 = tWff1 + WFF1_CNT;

    static int smem_set = 0;
    if (!smem_set){
        cudaFuncSetAttribute(attn4_kernel,
                             cudaFuncAttributeMaxDynamicSharedMemorySize, ATT_SMEM);
        cudaFuncSetAttribute(gemm_h,
                             cudaFuncAttributeMaxDynamicSharedMemorySize, GEMM_SMEM);
        smem_set = 1;
    }

    dim3 t328(32, 8);
    transp_w<<<dim3(3*HID/32, HID/32, NLAYERS), t328>>>(Wqkv, tWqkv, HID, 3*HID);
    transp_w<<<dim3(HID/32,   HID/32, NLAYERS), t328>>>(Wo,   tWo,   HID, HID);
    transp_w<<<dim3(FFN/32,   HID/32, NLAYERS), t328>>>(Wff1, tWff1, HID, FFN);
    transp_w<<<dim3(HID/32,   FFN/32, NLAYERS), t328>>>(Wff2, tWff2, FFN, HID);

    embed_kernel<<<TOK, 256>>>(input_ids, word_emb, pos_emb, emb_ln_s, emb_ln_b, x, x16);

    for (int l = 0; l < NLAYERS; l++){
        const __half* wqkv = tWqkv + (size_t)l * HID * 3 * HID;
        const float* bq   = bqkv + (size_t)l * 3 * HID;
        const __half* wo  = tWo   + (size_t)l * HID * HID;
        const float* bo_  = bo   + (size_t)l * HID;
        const float* s1   = ln1_s + (size_t)l * HID;
        const float* b1   = ln1_b + (size_t)l * HID;
        const __half* w1  = tWff1 + (size_t)l * HID * FFN;
        const float* bf1  = bff1 + (size_t)l * FFN;
        const __half* w2  = tWff2 + (size_t)l * FFN * HID;
        const float* bf2  = bff2 + (size_t)l * HID;
        const float* s2   = ln2_s + (size_t)l * HID;
        const float* b2   = ln2_b + (size_t)l * HID;

        // QKV: fp16 out
        gemm_h<<<dim3(3*HID/128, TOK/128), 256, GEMM_SMEM>>>(x16, wqkv, bq, nullptr, qkv16, TOK, 3*HID, HID, 2);
        // attention (fp16 in/out)
        attn4_kernel<<<dim3(SEQ/128, NH, BSZ), 256, ATT_SMEM>>>(qkv16, amask, attn16);
        // O-proj: fp32 out
        gemm_h<<<dim3(HID/128, TOK/128), 256, GEMM_SMEM>>>(attn16, wo, bo_, tmp, nullptr, TOK, HID, HID, 0);
        ln_residual_kernel<<<TOK, 256>>>(x, tmp, s1, b1, h1, h116);
        // FFN1: gelu + fp16 out
        gemm_h<<<dim3(FFN/128, TOK/128), 256, GEMM_SMEM>>>(h116, w1, bf1, nullptr, ffn16, TOK, FFN, HID, 1);
        // FFN2: fp32 out
        gemm_h<<<dim3(HID/128, TOK/128), 256, GEMM_SMEM>>>(ffn16, w2, bf2, tmp, nullptr, TOK, HID, FFN, 0);
        ln_residual_kernel<<<TOK, 256>>>(h1, tmp, s2, b2, x, x16);
    }

    float* out = (float*)d_out;
    cls_kernel<<<TOK, 288>>>(x, Wcls, bcls, logits, out + 1);
    crf_kernel<<<BSZ, 32>>>(logits, labels, crf_start, crf_end, crf_trans, res);
    finalize_kernel<<<1, 32>>>(res, out);
}

// round 17
// speedup vs baseline: 1.1332x; 1.0043x over previous
#include <cuda_runtime.h>
#include <cuda_fp16.h>
#include <math.h>
#include <stdint.h>

#define BSZ 16
#define SEQ 256
#define HID 768
#define TOK (BSZ*SEQ)      // 4096
#define FFN 3072
#define NH 12
#define HD 64
#define NT 9
#define NLAYERS 6

#define WQKV_CNT (NLAYERS*HID*3*HID)
#define WO_CNT   (NLAYERS*HID*HID)
#define WFF1_CNT (NLAYERS*HID*FFN)
#define WFF2_CNT (NLAYERS*FFN*HID)
#define WTOT_CNT (WQKV_CNT+WO_CNT+WFF1_CNT+WFF2_CNT)

// ---------------- scratch ----------------
__device__ float  g_x[TOK*HID];
__device__ float  g_h1[TOK*HID];
__device__ float  g_tmp[TOK*HID];
__device__ float  g_logits[TOK*NT];
__device__ float  g_res[BSZ];
__device__ __half g_qkv16[TOK*3*HID];
__device__ __half g_x16[TOK*HID];
__device__ __half g_h116[TOK*HID];
__device__ __half g_attn16[TOK*HID];
__device__ __half g_ffn16[(size_t)TOK*FFN];
__device__ __half g_wt16[(size_t)WTOT_CNT];   // transposed fp16 weights [N][K]

// ---------------- reductions ----------------
__device__ __forceinline__ float warpReduceSum(float v){
    #pragma unroll
    for (int o = 16; o; o >>= 1) v += __shfl_xor_sync(0xffffffffu, v, o);
    return v;
}
__device__ float blockReduceSum(float v, float* sh){
    __syncthreads();
    int lane = threadIdx.x & 31, wid = threadIdx.x >> 5;
    v = warpReduceSum(v);
    if (lane == 0) sh[wid] = v;
    __syncthreads();
    int nw = blockDim.x >> 5;
    v = (threadIdx.x < nw) ? sh[threadIdx.x] : 0.0f;
    if (wid == 0) v = warpReduceSum(v);
    if (threadIdx.x == 0) sh[0] = v;
    __syncthreads();
    return sh[0];
}

__device__ __forceinline__ float gelu_tanh(float x){
    float x3 = x * x * x;
    return 0.5f * x * (1.0f + tanhf(0.7978845608028654f * (x + 0.044715f * x3)));
}

// ---------------- mma / async / ldmatrix helpers ----------------
__device__ __forceinline__ void mma_f16(float* c, const uint32_t* a, const uint32_t* b){
    asm volatile(
        "mma.sync.aligned.m16n8k16.row.col.f32.f16.f16.f32 "
        "{%0,%1,%2,%3},{%4,%5,%6,%7},{%8,%9},{%0,%1,%2,%3};"
        : "+f"(c[0]), "+f"(c[1]), "+f"(c[2]), "+f"(c[3])
        : "r"(a[0]), "r"(a[1]), "r"(a[2]), "r"(a[3]), "r"(b[0]), "r"(b[1]));
}
__device__ __forceinline__ void cpasync16(const void* smem, const void* g){
    uint32_t s = (uint32_t)__cvta_generic_to_shared(smem);
    asm volatile("cp.async.cg.shared.global [%0], [%1], 16;" :: "r"(s), "l"(g));
}
#define CP_COMMIT() asm volatile("cp.async.commit_group;")
#define CP_WAIT(n)  asm volatile("cp.async.wait_group %0;" :: "n"(n))

__device__ __forceinline__ void ldsm_x4(uint32_t* r, const __half* p){
    uint32_t a = (uint32_t)__cvta_generic_to_shared(p);
    asm volatile("ldmatrix.sync.aligned.m8n8.x4.shared.b16 {%0,%1,%2,%3}, [%4];"
        : "=r"(r[0]), "=r"(r[1]), "=r"(r[2]), "=r"(r[3]) : "r"(a));
}

// ------ weight transpose + fp16: W[K][N] -> Wt[N][K], 128B-coalesced stores ---
// tile 64(k) x 32(n), block (32,8). Writes __half2: warp covers 64 k = 128B.
__global__ void transp_w(const float* __restrict__ src, __half* __restrict__ dst,
                         int K, int N){
    __shared__ float t[64][33];
    size_t off = (size_t)blockIdx.z * K * N;
    const float* s = src + off;
    __half* d = dst + off;
    int n0 = blockIdx.x * 32, k0 = blockIdx.y * 64;
    int tx = threadIdx.x, ty = threadIdx.y;
    #pragma unroll
    for (int i = 0; i < 8; i++){
        int kl = ty + i * 8;
        t[kl][tx] = s[(size_t)(k0 + kl) * N + n0 + tx];
    }
    __syncthreads();
    #pragma unroll
    for (int i = 0; i < 4; i++){
        int nl = ty + i * 8;
        __half2 h = __halves2half2(__float2half(t[tx*2][nl]),
                                   __float2half(t[tx*2 + 1][nl]));
        *(__half2*)&d[(size_t)(n0 + nl) * K + k0 + tx * 2] = h;
    }
}

// ---------------- embedding + LN ----------------
__global__ void embed_kernel(const int* __restrict__ ids,
                             const float* __restrict__ we,
                             const float* __restrict__ pe,
                             const float* __restrict__ gamma,
                             const float* __restrict__ beta,
                             float* __restrict__ out,
                             __half* __restrict__ out16){
    __shared__ float sh[32];
    int tok = blockIdx.x;
    int sI = tok % SEQ;
    int id = ids[tok];
    const float* wrow = we + (size_t)id * HID;
    const float* prow = pe + (size_t)sI * HID;
    float vals[3]; float lsum = 0.f;
    #pragma unroll
    for (int i = 0; i < 3; i++){
        int d = threadIdx.x + i * 256;
        float v = wrow[d] + prow[d];
        vals[i] = v; lsum += v;
    }
    float mean = blockReduceSum(lsum, sh) * (1.0f / HID);
    float lss = 0.f;
    #pragma unroll
    for (int i = 0; i < 3; i++){ float d0 = vals[i] - mean; lss += d0 * d0; }
    float var = blockReduceSum(lss, sh) * (1.0f / HID);
    float rstd = rsqrtf(var + 1e-12f);
    #pragma unroll
    for (int i = 0; i < 3; i++){
        int d = threadIdx.x + i * 256;
        float v = (vals[i] - mean) * rstd * gamma[d] + beta[d];
        out[(size_t)tok * HID + d] = v;
        out16[(size_t)tok * HID + d] = __float2half(v);
    }
}

// ---------------- residual + LN ----------------
__global__ void ln_residual_kernel(const float* __restrict__ a,
                                   const float* __restrict__ c,
                                   const float* __restrict__ gamma,
                                   const float* __restrict__ beta,
                                   float* __restrict__ out,
                                   __half* __restrict__ out16){
    __shared__ float sh[32];
    int tok = blockIdx.x;
    const float* ar = a + (size_t)tok * HID;
    const float* cr = c + (size_t)tok * HID;
    float vals[3]; float lsum = 0.f;
    #pragma unroll
    for (int i = 0; i < 3; i++){
        int d = threadIdx.x + i * 256;
        float v = ar[d] + cr[d];
        vals[i] = v; lsum += v;
    }
    float mean = blockReduceSum(lsum, sh) * (1.0f / HID);
    float lss = 0.f;
    #pragma unroll
    for (int i = 0; i < 3; i++){ float d0 = vals[i] - mean; lss += d0 * d0; }
    float var = blockReduceSum(lss, sh) * (1.0f / HID);
    float rstd = rsqrtf(var + 1e-12f);
    #pragma unroll
    for (int i = 0; i < 3; i++){
        int d = threadIdx.x + i * 256;
        float v = (vals[i] - mean) * rstd * gamma[d] + beta[d];
        out[(size_t)tok * HID + d] = v;
        out16[(size_t)tok * HID + d] = __float2half(v);
    }
}

// ================= fp16 TC GEMM, 128x128 tile, BK=32, ldmatrix ================
// act: 0 = fp32 out, 1 = gelu+fp16, 2 = plain fp16
#define ASH 40
#define STG_H (128*ASH)
#define GEMM_SMEM (2 * 2 * STG_H * 2)

__device__ __forceinline__ void g_fill(__half* as, __half* bs,
                                       const __half* __restrict__ A16,
                                       const __half* __restrict__ W16,
                                       int rowBase, int colBase, int K,
                                       int k0, int tid){
    int r = tid >> 1, c = (tid & 1) * 16;
    const __half* ag = A16 + (size_t)(rowBase + r) * K + k0 + c;
    __half* ad = as + r * ASH + c;
    cpasync16(ad, ag); cpasync16(ad + 8, ag + 8);
    const __half* bg = W16 + (size_t)(colBase + r) * K + k0 + c;
    __half* bd = bs + r * ASH + c;
    cpasync16(bd, bg); cpasync16(bd + 8, bg + 8);
}

__global__ void __launch_bounds__(256, 2)
gemm_h(const __half* __restrict__ A16,
       const __half* __restrict__ W16,
       const float* __restrict__ bias,
       float* __restrict__ C32,
       __half* __restrict__ C16,
       int M, int N, int K, int act){
    extern __shared__ char smraw[];
    __half* sm = (__half*)smraw;
    __half* As[2] = { sm,         sm + 2*STG_H };
    __half* Bs[2] = { sm + STG_H, sm + 3*STG_H };

    int tid = threadIdx.x;
    int wid = tid >> 5, lane = tid & 31;
    int warpRow = wid >> 1, warpCol = wid & 1;
    int gid = lane >> 2, tig = lane & 3;
    int rowBase = blockIdx.y * 128, colBase = blockIdx.x * 128;

    int lm_row = lane & 15;
    int lm_acol = (lane >> 4) << 3;
    int lm_brow = ((lane & 16) >> 1) + (lane & 7);
    int lm_bcol = lane & 8;

    float acc[2][8][4];
    #pragma unroll
    for (int mi = 0; mi < 2; mi++)
        #pragma unroll
        for (int ni = 0; ni < 8; ni++)
            #pragma unroll
            for (int j = 0; j < 4; j++) acc[mi][ni][j] = 0.f;

    int ntile = K >> 5;
    g_fill(As[0], Bs[0], A16, W16, rowBase, colBase, K, 0, tid);
    CP_COMMIT();

    for (int t = 0; t < ntile; t++){
        if (t + 1 < ntile){
            g_fill(As[(t+1)&1], Bs[(t+1)&1], A16, W16, rowBase, colBase, K, (t+1) << 5, tid);
            CP_COMMIT();
            CP_WAIT(1);
        } else {
            CP_WAIT(0);
        }
        __syncthreads();

        const __half* as = As[t & 1];
        const __half* bs = Bs[t & 1];
        #pragma unroll
        for (int sl = 0; sl < 2; sl++){
            int kb = sl * 16;
            uint32_t af[2][4], bf[8][2];
            #pragma unroll
            for (int mi = 0; mi < 2; mi++){
                int m0 = warpRow * 32 + mi * 16;
                ldsm_x4(af[mi], as + (m0 + lm_row) * ASH + kb + lm_acol);
            }
            #pragma unroll
            for (int np = 0; np < 4; np++){
                int n0 = warpCol * 64 + np * 16;
                uint32_t tb[4];
                ldsm_x4(tb, bs + (n0 + lm_brow) * ASH + kb + lm_bcol);
                bf[np*2][0]   = tb[0]; bf[np*2][1]   = tb[1];
                bf[np*2+1][0] = tb[2]; bf[np*2+1][1] = tb[3];
            }
            #pragma unroll
            for (int mi = 0; mi < 2; mi++)
                #pragma unroll
                for (int ni = 0; ni < 8; ni++)
                    mma_f16(acc[mi][ni], af[mi], bf[ni]);
        }
        __syncthreads();
    }

    #pragma unroll
    for (int mi = 0; mi < 2; mi++){
        int r0 = rowBase + warpRow * 32 + mi * 16 + gid;
        #pragma unroll
        for (int ni = 0; ni < 8; ni++){
            int cc = colBase + warpCol * 64 + ni * 8 + tig * 2;
            float b0 = bias[cc], b1 = bias[cc + 1];
            float v0 = acc[mi][ni][0] + b0, v1 = acc[mi][ni][1] + b1;
            float v2 = acc[mi][ni][2] + b0, v3 = acc[mi][ni][3] + b1;
            if (act == 1){
                v0 = gelu_tanh(v0); v1 = gelu_tanh(v1);
                v2 = gelu_tanh(v2); v3 = gelu_tanh(v3);
            }
            if (act == 0){
                *(float2*)&C32[(size_t)r0 * N + cc]       = make_float2(v0, v1);
                *(float2*)&C32[(size_t)(r0 + 8) * N + cc] = make_float2(v2, v3);
            } else {
                *(__half2*)&C16[(size_t)r0 * N + cc]       = __floats2half2_rn(v0, v1);
                *(__half2*)&C16[(size_t)(r0 + 8) * N + cc] = __floats2half2_rn(v2, v3);
            }
        }
    }
}

// ---------------- attention: fp16 flash attention, ldmatrix fragments ---------
#define AQ 72
#define ATT_H (128*AQ + 64*AQ + 64*AQ + 8*16*AQ)
#define ATT_SMEM (ATT_H*2 + 256*4)
__global__ void __launch_bounds__(256, 2)
attn4_kernel(const __half* __restrict__ qkv16,
             const int* __restrict__ amask,
             __half* __restrict__ out16){
    extern __shared__ char smraw[];
    __half* Qs = (__half*)smraw;
    __half* Ks = Qs + 128 * AQ;
    __half* Vt = Ks + 64 * AQ;
    __half* Pa = Vt + 64 * AQ;
    float*  bsm = (float*)(smraw + ATT_H * 2);
    int tid = threadIdx.x, w = tid >> 5, lane = tid & 31;
    int gid = lane >> 2, tig = lane & 3;
    int qb = blockIdx.x * 128, h = blockIdx.y, b = blockIdx.z;
    const size_t rs = 3 * HID;
    const __half* base = qkv16 + (size_t)b * SEQ * rs;
    __half* Pw = Pa + w * 16 * AQ;
    int m0 = w * 16;

    int lm_row = lane & 15;
    int lm_acol = (lane >> 4) << 3;
    int lm_brow = ((lane & 16) >> 1) + (lane & 7);
    int lm_bcol = lane & 8;

    bsm[tid] = (1.0f - (float)amask[b * SEQ + tid]) * -1e9f;

    {
        int r = tid >> 1, c0 = (tid & 1) * 32;
        const __half2* src = (const __half2*)(base + (size_t)(qb + r) * rs + h * HD + c0);
        __half2* dst = (__half2*)(Qs + r * AQ + c0);
        __half2 sc = __floats2half2_rn(0.125f, 0.125f);
        #pragma unroll
        for (int j = 0; j < 16; j++) dst[j] = __hmul2(src[j], sc);
    }

    float of[8][4];
    #pragma unroll
    for (int ni = 0; ni < 8; ni++)
        #pragma unroll
        for (int j = 0; j < 4; j++) of[ni][j] = 0.f;
    float mrow0 = -1e30f, mrow1 = -1e30f, lrow0 = 0.f, lrow1 = 0.f;

    for (int c = 0; c < 4; c++){
        __syncthreads();
        {
            int k = tid >> 2, d0 = (tid & 3) * 16;
            const __half* ks = base + (size_t)(c * 64 + k) * rs + HID + h * HD + d0;
            const __half* vs = base + (size_t)(c * 64 + k) * rs + 2 * HID + h * HD + d0;
            *(uint4*)(Ks + k * AQ + d0)     = *(const uint4*)ks;
            *(uint4*)(Ks + k * AQ + d0 + 8) = *(const uint4*)(ks + 8);
            __half vloc[16];
            *(uint4*)vloc       = *(const uint4*)vs;
            *(uint4*)(vloc + 8) = *(const uint4*)(vs + 8);
            #pragma unroll
            for (int j = 0; j < 16; j++)
                Vt[(d0 + j) * AQ + k] = vloc[j];
        }
        __syncthreads();

        float sc[8][4];
        #pragma unroll
        for (int ni = 0; ni < 8; ni++)
            #pragma unroll
            for (int j = 0; j < 4; j++) sc[ni][j] = 0.f;
        #pragma unroll
        for (int sl = 0; sl < 4; sl++){
            int kb = sl * 16;
            uint32_t a[4], bf[8][2];
            ldsm_x4(a, Qs + (m0 + lm_row) * AQ + kb + lm_acol);
            #pragma unroll
            for (int np = 0; np < 4; np++){
                uint32_t tb[4];
                ldsm_x4(tb, Ks + (np * 16 + lm_brow) * AQ + kb + lm_bcol);
                bf[np*2][0]   = tb[0]; bf[np*2][1]   = tb[1];
                bf[np*2+1][0] = tb[2]; bf[np*2+1][1] = tb[3];
            }
            #pragma unroll
            for (int ni = 0; ni < 8; ni++)
                mma_f16(sc[ni], a, bf[ni]);
        }

        float mx0 = -1e30f, mx1 = -1e30f;
        #pragma unroll
        for (int ni = 0; ni < 8; ni++){
            int key = c * 64 + ni * 8 + tig * 2;
            float b0 = bsm[key], b1 = bsm[key + 1];
            sc[ni][0] += b0; sc[ni][1] += b1;
            sc[ni][2] += b0; sc[ni][3] += b1;
            mx0 = fmaxf(mx0, fmaxf(sc[ni][0], sc[ni][1]));
            mx1 = fmaxf(mx1, fmaxf(sc[ni][2], sc[ni][3]));
        }
        mx0 = fmaxf(mx0, __shfl_xor_sync(0xffffffffu, mx0, 1));
        mx0 = fmaxf(mx0, __shfl_xor_sync(0xffffffffu, mx0, 2));
        mx1 = fmaxf(mx1, __shfl_xor_sync(0xffffffffu, mx1, 1));
        mx1 = fmaxf(mx1, __shfl_xor_sync(0xffffffffu, mx1, 2));
        float nm0 = fmaxf(mrow0, mx0), nm1 = fmaxf(mrow1, mx1);
        float corr0 = __expf(mrow0 - nm0), corr1 = __expf(mrow1 - nm1);
        float sum0 = 0.f, sum1 = 0.f;
        #pragma unroll
        for (int ni = 0; ni < 8; ni++){
            float p0 = __expf(sc[ni][0] - nm0);
            float p1 = __expf(sc[ni][1] - nm0);
            float p2 = __expf(sc[ni][2] - nm1);
            float p3 = __expf(sc[ni][3] - nm1);
            sum0 += p0 + p1; sum1 += p2 + p3;
            int n0 = ni * 8 + tig * 2;
            *(__half2*)(Pw + gid * AQ + n0)       = __floats2half2_rn(p0, p1);
            *(__half2*)(Pw + (gid + 8) * AQ + n0) = __floats2half2_rn(p2, p3);
        }
        sum0 += __shfl_xor_sync(0xffffffffu, sum0, 1);
        sum0 += __shfl_xor_sync(0xffffffffu, sum0, 2);
        sum1 += __shfl_xor_sync(0xffffffffu, sum1, 1);
        sum1 += __shfl_xor_sync(0xffffffffu, sum1, 2);
        lrow0 = lrow0 * corr0 + sum0;
        lrow1 = lrow1 * corr1 + sum1;
        mrow0 = nm0; mrow1 = nm1;
        #pragma unroll
        for (int ni = 0; ni < 8; ni++){
            of[ni][0] *= corr0; of[ni][1] *= corr0;
            of[ni][2] *= corr1; of[ni][3] *= corr1;
        }
        __syncwarp();

        #pragma unroll
        for (int sl = 0; sl < 4; sl++){
            int kb = sl * 16;
            uint32_t a[4], bf[8][2];
            ldsm_x4(a, Pw + lm_row * AQ + kb + lm_acol);
            #pragma unroll
            for (int np = 0; np < 4; np++){
                uint32_t tb[4];
                ldsm_x4(tb, Vt + (np * 16 + lm_brow) * AQ + kb + lm_bcol);
                bf[np*2][0]   = tb[0]; bf[np*2][1]   = tb[1];
                bf[np*2+1][0] = tb[2]; bf[np*2+1][1] = tb[3];
            }
            #pragma unroll
            for (int ni = 0; ni < 8; ni++)
                mma_f16(of[ni], a, bf[ni]);
        }
        __syncwarp();
    }

    float inv0 = 1.0f / lrow0, inv1 = 1.0f / lrow1;
    int q0 = qb + m0 + gid, q1 = q0 + 8;
    #pragma unroll
    for (int ni = 0; ni < 8; ni++){
        int d = ni * 8 + tig * 2;
        *(__half2*)&out16[(size_t)(b * SEQ + q0) * HID + h * HD + d] =
            __floats2half2_rn(of[ni][0] * inv0, of[ni][1] * inv0);
        *(__half2*)&out16[(size_t)(b * SEQ + q1) * HID + h * HD + d] =
            __floats2half2_rn(of[ni][2] * inv1, of[ni][3] * inv1);
    }
}

// ---------------- classifier: writes scratch logits AND d_out+1 ---------------
__global__ void cls_kernel(const float* __restrict__ x,
                           const float* __restrict__ W,
                           const float* __restrict__ bias,
                           float* __restrict__ logits,
                           float* __restrict__ out1){
    __shared__ float xs[HID];
    int tok = blockIdx.x;
    for (int d = threadIdx.x; d < HID; d += blockDim.x)
        xs[d] = x[(size_t)tok * HID + d];
    __syncthreads();
    int w = threadIdx.x >> 5, lane = threadIdx.x & 31;
    float acc = 0.f;
    for (int d = lane; d < HID; d += 32)
        acc = fmaf(xs[d], W[d * NT + w], acc);
    acc = warpReduceSum(acc);
    if (lane == 0){
        float v = acc + bias[w];
        logits[tok * NT + w] = v;
        out1[tok * NT + w] = v;
    }
}

// ---------------- CRF ----------------
__global__ void crf_kernel(const float* __restrict__ logits,
                           const int* __restrict__ labels,
                           const float* __restrict__ cstart,
                           const float* __restrict__ cend,
                           const float* __restrict__ ctrans,
                           float* __restrict__ res){
    __shared__ float score[NT];
    __shared__ float tr[NT * NT];
    __shared__ float st[NT], en[NT];
    int b = blockIdx.x, tid = threadIdx.x;
    for (int i = tid; i < NT * NT; i += 32) tr[i] = ctrans[i];
    if (tid < NT){ st[tid] = cstart[tid]; en[tid] = cend[tid]; }
    const float* lg = logits + (size_t)b * SEQ * NT;
    const int* lab = labels + b * SEQ;
    if (tid < NT) score[tid] = st[tid] + lg[tid];
    __syncwarp();
    for (int s = 1; s < SEQ; s++){
        float nxt = 0.f;
        if (tid < NT){
            float m = -INFINITY;
            #pragma unroll
            for (int i = 0; i < NT; i++) m = fmaxf(m, score[i] + tr[i * NT + tid]);
            float sum = 0.f;
            #pragma unroll
            for (int i = 0; i < NT; i++) sum += expf(score[i] + tr[i * NT + tid] - m);
            nxt = m + logf(sum) + lg[s * NT + tid];
        }
        bool msk = (lab[s] != -100);
        __syncwarp();
        if (tid < NT && msk) score[tid] = nxt;
        __syncwarp();
    }
    if (tid == 0){
        float m = -INFINITY;
        for (int t = 0; t < NT; t++) m = fmaxf(m, score[t] + en[t]);
        float sum = 0.f;
        for (int t = 0; t < NT; t++) sum += expf(score[t] + en[t] - m);
        float denom = m + logf(sum);
        int l0 = lab[0];
        int tag_prev = (l0 == -100) ? 0 : l0;
        float num = st[tag_prev] + lg[tag_prev];
        int cnt = 1;
        for (int s = 1; s < SEQ; s++){
            int ls = lab[s];
            bool msk = (ls != -100);
            int tg = msk ? ls : 0;
            if (msk){
                num += tr[tag_prev * NT + tg] + lg[s * NT + tg];
                cnt++;
            }
            tag_prev = tg;
        }
        int seq_end = cnt - 1;
        int le = lab[seq_end];
        int last_tag = (le == -100) ? 0 : le;
        num += en[last_tag];
        res[b] = num - denom;
    }
}

// ---------------- finalize: loss only ----------------
__global__ void finalize_kernel(const float* __restrict__ res,
                                float* __restrict__ out){
    if (threadIdx.x == 0){
        float s = 0.f;
        for (int b = 0; b < BSZ; b++) s += res[b];
        out[0] = -s / BSZ;
    }
}

// ---------------- launch ----------------
extern "C" void kernel_launch(void* const* d_in, const int* in_sizes, int n_in,
                              void* d_out, int out_size){
    const int*   input_ids = (const int*)  d_in[0];
    const int*   amask     = (const int*)  d_in[1];
    const int*   labels    = (const int*)  d_in[2];
    const float* word_emb  = (const float*)d_in[3];
    const float* pos_emb   = (const float*)d_in[4];
    const float* emb_ln_s  = (const float*)d_in[5];
    const float* emb_ln_b  = (const float*)d_in[6];
    const float* Wqkv      = (const float*)d_in[7];
    const float* bqkv      = (const float*)d_in[8];
    const float* Wo        = (const float*)d_in[9];
    const float* bo        = (const float*)d_in[10];
    const float* ln1_s     = (const float*)d_in[11];
    const float* ln1_b     = (const float*)d_in[12];
    const float* Wff1      = (const float*)d_in[13];
    const float* bff1      = (const float*)d_in[14];
    const float* Wff2      = (const float*)d_in[15];
    const float* bff2      = (const float*)d_in[16];
    const float* ln2_s     = (const float*)d_in[17];
    const float* ln2_b     = (const float*)d_in[18];
    const float* Wcls      = (const float*)d_in[19];
    const float* bcls      = (const float*)d_in[20];
    const float* crf_start = (const float*)d_in[21];
    const float* crf_end   = (const float*)d_in[22];
    const float* crf_trans = (const float*)d_in[23];

    float *x, *h1, *tmp, *logits, *res;
    __half *qkv16, *x16, *h116, *attn16, *ffn16, *wt16;
    cudaGetSymbolAddress((void**)&x,      g_x);
    cudaGetSymbolAddress((void**)&h1,     g_h1);
    cudaGetSymbolAddress((void**)&tmp,    g_tmp);
    cudaGetSymbolAddress((void**)&logits, g_logits);
    cudaGetSymbolAddress((void**)&res,    g_res);
    cudaGetSymbolAddress((void**)&qkv16,  g_qkv16);
    cudaGetSymbolAddress((void**)&x16,    g_x16);
    cudaGetSymbolAddress((void**)&h116,   g_h116);
    cudaGetSymbolAddress((void**)&attn16, g_attn16);
    cudaGetSymbolAddress((void**)&ffn16,  g_ffn16);
    cudaGetSymbolAddress((void**)&wt16,   g_wt16);

    __half* tWqkv = wt16;
    __half* tWo   = tWqkv + WQKV_CNT;
    __half* tWff1 = tWo   + WO_CNT;
    __half* tWff2 = tWff1 + WFF1_CNT;

    static int smem_set = 0;
    if (!smem_set){
        cudaFuncSetAttribute(attn4_kernel,
                             cudaFuncAttributeMaxDynamicSharedMemorySize, ATT_SMEM);
        cudaFuncSetAttribute(gemm_h,
                             cudaFuncAttributeMaxDynamicSharedMemorySize, GEMM_SMEM);
        smem_set = 1;
    }

    dim3 t328(32, 8);
    // tile: 32 n (grid.x) x 64 k (grid.y)
    transp_w<<<dim3(3*HID/32, HID/64, NLAYERS), t328>>>(Wqkv, tWqkv, HID, 3*HID);
    transp_w<<<dim3(HID/32,   HID/64, NLAYERS), t328>>>(Wo,   tWo,   HID, HID);
    transp_w<<<dim3(FFN/32,   HID/64, NLAYERS), t328>>>(Wff1, tWff1, HID, FFN);
    transp_w<<<dim3(HID/32,   FFN/64, NLAYERS), t328>>>(Wff2, tWff2, FFN, HID);

    embed_kernel<<<TOK, 256>>>(input_ids, word_emb, pos_emb, emb_ln_s, emb_ln_b, x, x16);

    for (int l = 0; l < NLAYERS; l++){
        const __half* wqkv = tWqkv + (size_t)l * HID * 3 * HID;
        const float* bq   = bqkv + (size_t)l * 3 * HID;
        const __half* wo  = tWo   + (size_t)l * HID * HID;
        const float* bo_  = bo   + (size_t)l * HID;
        const float* s1   = ln1_s + (size_t)l * HID;
        const float* b1   = ln1_b + (size_t)l * HID;
        const __half* w1  = tWff1 + (size_t)l * HID * FFN;
        const float* bf1  = bff1 + (size_t)l * FFN;
        const __half* w2  = tWff2 + (size_t)l * FFN * HID;
        const float* bf2  = bff2 + (size_t)l * HID;
        const float* s2   = ln2_s + (size_t)l * HID;
        const float* b2   = ln2_b + (size_t)l * HID;

        // QKV: fp16 out
        gemm_h<<<dim3(3*HID/128, TOK/128), 256, GEMM_SMEM>>>(x16, wqkv, bq, nullptr, qkv16, TOK, 3*HID, HID, 2);
        // attention (fp16 in/out)
        attn4_kernel<<<dim3(SEQ/128, NH, BSZ), 256, ATT_SMEM>>>(qkv16, amask, attn16);
        // O-proj: fp32 out
        gemm_h<<<dim3(HID/128, TOK/128), 256, GEMM_SMEM>>>(attn16, wo, bo_, tmp, nullptr, TOK, HID, HID, 0);
        ln_residual_kernel<<<TOK, 256>>>(x, tmp, s1, b1, h1, h116);
        // FFN1: gelu + fp16 out
        gemm_h<<<dim3(FFN/128, TOK/128), 256, GEMM_SMEM>>>(h116, w1, bf1, nullptr, ffn16, TOK, FFN, HID, 1);
        // FFN2: fp32 out
        gemm_h<<<dim3(HID/128, TOK/128), 256, GEMM_SMEM>>>(ffn16, w2, bf2, tmp, nullptr, TOK, HID, FFN, 0);
        ln_residual_kernel<<<TOK, 256>>>(h1, tmp, s2, b2, x, x16);
    }

    float* out = (float*)d_out;
    cls_kernel<<<TOK, 288>>>(x, Wcls, bcls, logits, out + 1);
    crf_kernel<<<BSZ, 32>>>(logits, labels, crf_start, crf_end, crf_trans, res);
    finalize_kernel<<<1, 32>>>(res, out);
}